// round 1
// baseline (speedup 1.0000x reference)
#include <cuda_runtime.h>

namespace {

constexpr int Hh = 8, Ll = 2048, Dd = 512;
constexpr float PIf = 3.14159265358979323846f;

struct cplx { float x, y; };
__device__ __forceinline__ cplx cadd(cplx a, cplx b){ return {a.x+b.x, a.y+b.y}; }
__device__ __forceinline__ cplx csub(cplx a, cplx b){ return {a.x-b.x, a.y-b.y}; }
__device__ __forceinline__ cplx cmul(cplx a, cplx b){ return {a.x*b.x - a.y*b.y, a.x*b.y + a.y*b.x}; }

// 8-point DFT, natural order in/out. S = -1 forward (e^{-2pi i nk/8}), +1 inverse.
template<int S>
__device__ __forceinline__ void dft8(cplx v[8]) {
  const float r = 0.70710678118654752440f;
  cplx a0=cadd(v[0],v[4]), a1=cadd(v[1],v[5]), a2=cadd(v[2],v[6]), a3=cadd(v[3],v[7]);
  cplx b0=csub(v[0],v[4]), b1=csub(v[1],v[5]), b2=csub(v[2],v[6]), b3=csub(v[3],v[7]);
  b1 = cmul(b1, cplx{ r, S * r});                     // W8^{S*1}
  b2 = (S < 0) ? cplx{ b2.y, -b2.x} : cplx{-b2.y, b2.x}; // * (∓i)
  b3 = cmul(b3, cplx{-r, S * r});                     // W8^{S*3}
  // DFT4 on a -> even outputs
  cplx e0=cadd(a0,a2), e1=cadd(a1,a3), o0=csub(a0,a2);
  cplx t1=csub(a1,a3);
  cplx o1 = (S < 0) ? cplx{ t1.y, -t1.x} : cplx{-t1.y, t1.x};
  v[0]=cadd(e0,e1); v[4]=csub(e0,e1); v[2]=cadd(o0,o1); v[6]=csub(o0,o1);
  // DFT4 on b -> odd outputs
  cplx f0=cadd(b0,b2), f1=cadd(b1,b3), p0=csub(b0,b2);
  cplx t2=csub(b1,b3);
  cplx p1 = (S < 0) ? cplx{ t2.y, -t2.x} : cplx{-t2.y, t2.x};
  v[1]=cadd(f0,f1); v[5]=csub(f0,f1); v[3]=cadd(p0,p1); v[7]=csub(p0,p1);
}

// Bank-conflict-free swizzle for logical index 64a + 8b + c (a,b,c in 0..7).
// Low 4 phys bits = (b1^c2, c2^a1, c1^b0, c0^a0): exactly 2-to-1 on each of
// the three warp access patterns -> 2 phases, zero conflict penalty for 8B.
__device__ __forceinline__ int swz(int a, int b, int c) {
  int a0 = a & 1, a1 = (a >> 1) & 1;
  int b0 = b & 1, b1 = (b >> 1) & 1, b2 = (b >> 2) & 1;
  int c0 = c & 1, c1 = (c >> 1) & 1, c2 = (c >> 2) & 1;
  return (a << 6) | (b2 << 5) | (b0 << 4)
       | ((b1 ^ c2) << 3) | ((c2 ^ a1) << 2) | ((c1 ^ b0) << 1) | (c0 ^ a0);
}

// One block = one (h,l): 4 pair-rows (pb=0..3 pairing batches pb and pb+4),
// 64 threads per pair-row. Radix-8 Stockham-free FFT512 (DIF fwd, digit-rev
// spectrum, DIT inv), spectral gate folded into the digit-reversed domain.
__global__ void __launch_bounds__(256)
sgn_fft_kernel(const float* __restrict__ x, const float* __restrict__ wgt,
               float* __restrict__ out)
{
  __shared__ float2 sm[4][512];
  const int tid = threadIdx.x;
  const int s   = tid >> 6;   // pair-row in block == pb
  const int t   = tid & 63;
  const int hl  = blockIdx.x;
  const int h   = hl >> 11;
  const int l   = hl & 2047;
  const int pb  = s;

  const size_t row1 = ((size_t)(((pb    ) * Hh + h) * Ll + l)) * Dd;
  const size_t row2 = ((size_t)(((pb + 4) * Hh + h) * Ll + l)) * Dd;
  const float2* __restrict__ wrow =
      reinterpret_cast<const float2*>(wgt) + (size_t)(h * Ll + l) * Dd;

  cplx v[8];
  const float* __restrict__ x1 = x + row1;
  const float* __restrict__ x2 = x + row2;

  // z = x1 + i*x2, loaded with n = 64*n2 + t (t = 8*n1 + n0)
#pragma unroll
  for (int n2 = 0; n2 < 8; ++n2) {
    v[n2].x = __ldg(&x1[(n2 << 6) + t]);
    v[n2].y = __ldg(&x2[(n2 << 6) + t]);
  }

  // ---- forward stage 1: DFT over n2 -> k0, twiddle e^{-2pi i * t * k0 / 512}
  dft8<-1>(v);
  {
    float sn, cs; __sincosf(-2.f * PIf * (float)t * (1.f / 512.f), &sn, &cs);
    cplx w1{cs, sn}, wk = w1;
#pragma unroll
    for (int k0 = 1; k0 < 8; ++k0) { v[k0] = cmul(v[k0], wk); if (k0 < 7) wk = cmul(wk, w1); }
  }
  {
    const int n1 = t >> 3, n0 = t & 7;
#pragma unroll
    for (int k0 = 0; k0 < 8; ++k0)
      sm[s][swz(k0, n1, n0)] = make_float2(v[k0].x, v[k0].y);
  }
  __syncthreads();

  // ---- forward stage 2: thread (k0, n0), DFT over n1 -> k1, twiddle e^{-2pi i n0 k1/64}
  const int k0 = t >> 3;
  const int n0 = t & 7;
#pragma unroll
  for (int j = 0; j < 8; ++j) { float2 f = sm[s][swz(k0, j, n0)]; v[j] = {f.x, f.y}; }
  dft8<-1>(v);
  {
    float sn, cs; __sincosf(-2.f * PIf * (float)n0 * (1.f / 64.f), &sn, &cs);
    cplx w1{cs, sn}, wk = w1;
#pragma unroll
    for (int k1 = 1; k1 < 8; ++k1) { v[k1] = cmul(v[k1], wk); if (k1 < 7) wk = cmul(wk, w1); }
  }
#pragma unroll
  for (int k1 = 0; k1 < 8; ++k1)
    sm[s][swz(k0, k1, n0)] = make_float2(v[k1].x, v[k1].y);
  __syncthreads();

  // ---- forward stage 3 (registers): thread (k0, k1), DFT over n0 -> k2
  const int k1 = t & 7;
#pragma unroll
  for (int c = 0; c < 8; ++c) { float2 f = sm[s][swz(k0, k1, c)]; v[c] = {f.x, f.y}; }
  dft8<-1>(v);
  // v[k2] = Z[k] at k = k0 + 8*k1 + 64*k2 (digit-reversed storage)

  // ---- spectral gate: U_k = Z_k * (W_k + conj(W_{-k})) / 1024
  // (1/1024 = the 1/2 of the Hermitian symmetrization * 1/512 IFFT norm)
  {
    const int kb = k0 + (k1 << 3);
#pragma unroll
    for (int k2 = 0; k2 < 8; ++k2) {
      const int k = kb + (k2 << 6);
      const float2 wk = __ldg(&wrow[k]);
      const float2 wm = __ldg(&wrow[(512 - k) & 511]);
      cplx V{ (wk.x + wm.x) * (1.f / 1024.f), (wk.y - wm.y) * (1.f / 1024.f) };
      v[k2] = cmul(v[k2], V);
    }
  }

  // ---- inverse stage 3': IDFT over k2 -> n0', twiddle e^{+2pi i n0' k1/64}
  dft8<1>(v);
  {
    float sn, cs; __sincosf(2.f * PIf * (float)k1 * (1.f / 64.f), &sn, &cs);
    cplx w1{cs, sn}, wk = w1;
#pragma unroll
    for (int n = 1; n < 8; ++n) { v[n] = cmul(v[n], wk); if (n < 7) wk = cmul(wk, w1); }
  }
#pragma unroll
  for (int c = 0; c < 8; ++c)
    sm[s][swz(k0, k1, c)] = make_float2(v[c].x, v[c].y);
  __syncthreads();

  // ---- inverse stage 2': thread (k0, n0), IDFT over k1 -> n1,
  //      twiddle e^{+2pi i (8*n1+n0)*k0/512}
#pragma unroll
  for (int j = 0; j < 8; ++j) { float2 f = sm[s][swz(k0, j, n0)]; v[j] = {f.x, f.y}; }
  dft8<1>(v);
  {
    float sn, cs;
    __sincosf(2.f * PIf * (float)(k0 * n0) * (1.f / 512.f), &sn, &cs);
    cplx w0{cs, sn};
    __sincosf(2.f * PIf * (float)k0 * (1.f / 64.f), &sn, &cs);
    cplx ws{cs, sn};
#pragma unroll
    for (int n1 = 0; n1 < 8; ++n1) { v[n1] = cmul(v[n1], w0); if (n1 < 7) w0 = cmul(w0, ws); }
  }
#pragma unroll
  for (int n1 = 0; n1 < 8; ++n1)
    sm[s][swz(k0, n1, n0)] = make_float2(v[n1].x, v[n1].y);
  __syncthreads();

  // ---- inverse stage 1': thread t=(n1,n0), IDFT over k0 -> n2, store
#pragma unroll
  for (int a = 0; a < 8; ++a) { float2 f = sm[s][swz(a, t >> 3, t & 7)]; v[a] = {f.x, f.y}; }
  dft8<1>(v);

  float* __restrict__ o1 = out + row1;
  float* __restrict__ o2 = out + row2;
#pragma unroll
  for (int n2 = 0; n2 < 8; ++n2) {
    o1[(n2 << 6) + t] = v[n2].x;   // Re -> batch pb
    o2[(n2 << 6) + t] = v[n2].y;   // Im -> batch pb+4
  }
}

} // namespace

extern "C" void kernel_launch(void* const* d_in, const int* in_sizes, int n_in,
                              void* d_out, int out_size) {
  const float* x   = (const float*)d_in[0];
  // d_in[1] is the (unused) mask
  const float* wgt = (const float*)d_in[2];
  float* out       = (float*)d_out;
  sgn_fft_kernel<<<Hh * Ll, 256>>>(x, wgt, out);
}

// round 2
// speedup vs baseline: 1.2099x; 1.2099x over previous
#include <cuda_runtime.h>

namespace {

constexpr int Hh = 8, Ll = 2048, Dd = 512;
constexpr float PIf = 3.14159265358979323846f;

struct cplx { float x, y; };
__device__ __forceinline__ cplx cadd(cplx a, cplx b){ return {a.x+b.x, a.y+b.y}; }
__device__ __forceinline__ cplx csub(cplx a, cplx b){ return {a.x-b.x, a.y-b.y}; }
__device__ __forceinline__ cplx cmul(cplx a, cplx b){ return {a.x*b.x - a.y*b.y, a.x*b.y + a.y*b.x}; }

// 8-point DFT, natural order in/out. S = -1 forward, +1 inverse.
template<int S>
__device__ __forceinline__ void dft8(cplx v[8]) {
  const float r = 0.70710678118654752440f;
  cplx a0=cadd(v[0],v[4]), a1=cadd(v[1],v[5]), a2=cadd(v[2],v[6]), a3=cadd(v[3],v[7]);
  cplx b0=csub(v[0],v[4]), b1=csub(v[1],v[5]), b2=csub(v[2],v[6]), b3=csub(v[3],v[7]);
  b1 = cmul(b1, cplx{ r, S * r});
  b2 = (S < 0) ? cplx{ b2.y, -b2.x} : cplx{-b2.y, b2.x};
  b3 = cmul(b3, cplx{-r, S * r});
  cplx e0=cadd(a0,a2), e1=cadd(a1,a3), o0=csub(a0,a2);
  cplx t1=csub(a1,a3);
  cplx o1 = (S < 0) ? cplx{ t1.y, -t1.x} : cplx{-t1.y, t1.x};
  v[0]=cadd(e0,e1); v[4]=csub(e0,e1); v[2]=cadd(o0,o1); v[6]=csub(o0,o1);
  cplx f0=cadd(b0,b2), f1=cadd(b1,b3), p0=csub(b0,b2);
  cplx t2=csub(b1,b3);
  cplx p1 = (S < 0) ? cplx{ t2.y, -t2.x} : cplx{-t2.y, t2.x};
  v[1]=cadd(f0,f1); v[5]=csub(f0,f1); v[3]=cadd(p0,p1); v[7]=csub(p0,p1);
}

// Bank-conflict-benign swizzle for logical index 64a + 8b + c (a,b,c in 0..7).
__device__ __forceinline__ int swz(int a, int b, int c) {
  int a0 = a & 1, a1 = (a >> 1) & 1;
  int b0 = b & 1, b1 = (b >> 1) & 1, b2 = (b >> 2) & 1;
  int c0 = c & 1, c1 = (c >> 1) & 1, c2 = (c >> 2) & 1;
  return (a << 6) | (b2 << 5) | (b0 << 4)
       | ((b1 ^ c2) << 3) | ((c2 ^ a1) << 2) | ((c1 ^ b0) << 1) | (c0 ^ a0);
}

// One block = one (h,l): 4 pair-rows (pb pairs batches pb and pb+4),
// 64 threads per pair-row. Radix-8 FFT512 (DIF fwd, digit-rev spectrum,
// DIT inv). The symmetrized gate V is staged into smem once per block
// with coalesced loads (it is shared by all 4 pair-rows).
__global__ void __launch_bounds__(256)
sgn_fft_kernel(const float* __restrict__ x, const float* __restrict__ wgt,
               float* __restrict__ out)
{
  __shared__ float2 sm[4][512];
  __shared__ float2 Vsm[512];

  const int tid = threadIdx.x;
  const int s   = tid >> 6;
  const int t   = tid & 63;
  const int hl  = blockIdx.x;
  const int h   = hl >> 11;
  const int l   = hl & 2047;

  const float2* __restrict__ wrow =
      reinterpret_cast<const float2*>(wgt) + (size_t)(h * Ll + l) * Dd;

  // ---- stage gate into smem (coalesced): V_k = (W_k + conj(W_{-k})) / 1024
  // (1/2 from Hermitian symmetrization * 1/512 IFFT norm). Ordered before
  // first use by the stage-1 __syncthreads below.
#pragma unroll
  for (int i = tid; i < 512; i += 256) {
    float2 wk = __ldg(&wrow[i]);
    float2 wm = __ldg(&wrow[(512 - i) & 511]);
    Vsm[i] = make_float2((wk.x + wm.x) * (1.f / 1024.f),
                         (wk.y - wm.y) * (1.f / 1024.f));
  }

  const size_t row1 = ((size_t)(((s    ) * Hh + h) * Ll + l)) * Dd;
  const size_t row2 = ((size_t)(((s + 4) * Hh + h) * Ll + l)) * Dd;
  const float* __restrict__ x1 = x + row1;
  const float* __restrict__ x2 = x + row2;

  cplx v[8];
  // z = x1 + i*x2, n = 64*n2 + t
#pragma unroll
  for (int n2 = 0; n2 < 8; ++n2) {
    v[n2].x = __ldg(&x1[(n2 << 6) + t]);
    v[n2].y = __ldg(&x2[(n2 << 6) + t]);
  }

  // ---- forward stage 1: DFT over n2 -> k0, twiddle e^{-2pi i t k0/512}
  dft8<-1>(v);
  {
    float sn, cs; __sincosf(-2.f * PIf * (float)t * (1.f / 512.f), &sn, &cs);
    cplx w1{cs, sn}, wk = w1;
#pragma unroll
    for (int k = 1; k < 8; ++k) { v[k] = cmul(v[k], wk); if (k < 7) wk = cmul(wk, w1); }
  }
  {
    const int n1 = t >> 3, n0 = t & 7;
#pragma unroll
    for (int k = 0; k < 8; ++k)
      sm[s][swz(k, n1, n0)] = make_float2(v[k].x, v[k].y);
  }
  __syncthreads();

  // ---- forward stage 2: thread (k0, n0), DFT over n1 -> k1, twiddle e^{-2pi i n0 k1/64}
  const int k0 = t >> 3;
  const int n0 = t & 7;
#pragma unroll
  for (int j = 0; j < 8; ++j) { float2 f = sm[s][swz(k0, j, n0)]; v[j] = {f.x, f.y}; }
  dft8<-1>(v);
  {
    float sn, cs; __sincosf(-2.f * PIf * (float)n0 * (1.f / 64.f), &sn, &cs);
    cplx w1{cs, sn}, wk = w1;
#pragma unroll
    for (int k = 1; k < 8; ++k) { v[k] = cmul(v[k], wk); if (k < 7) wk = cmul(wk, w1); }
  }
#pragma unroll
  for (int k = 0; k < 8; ++k)
    sm[s][swz(k0, k, n0)] = make_float2(v[k].x, v[k].y);
  __syncthreads();

  // ---- forward stage 3 (registers): thread (k0, k1), DFT over n0 -> k2
  const int k1 = t & 7;
#pragma unroll
  for (int c = 0; c < 8; ++c) { float2 f = sm[s][swz(k0, k1, c)]; v[c] = {f.x, f.y}; }
  dft8<-1>(v);
  // v[k2] = Z[k] at k = k0 + 8*k1 + 64*k2

  // ---- spectral gate from smem (2-way conflict only)
  {
    const int kb = k0 + (k1 << 3);
#pragma unroll
    for (int k2 = 0; k2 < 8; ++k2) {
      float2 Vv = Vsm[kb + (k2 << 6)];
      v[k2] = cmul(v[k2], cplx{Vv.x, Vv.y});
    }
  }

  // ---- inverse stage 3': IDFT over k2 -> n0', twiddle e^{+2pi i n0' k1/64}
  dft8<1>(v);
  {
    float sn, cs; __sincosf(2.f * PIf * (float)k1 * (1.f / 64.f), &sn, &cs);
    cplx w1{cs, sn}, wk = w1;
#pragma unroll
    for (int n = 1; n < 8; ++n) { v[n] = cmul(v[n], wk); if (n < 7) wk = cmul(wk, w1); }
  }
#pragma unroll
  for (int c = 0; c < 8; ++c)
    sm[s][swz(k0, k1, c)] = make_float2(v[c].x, v[c].y);
  __syncthreads();

  // ---- inverse stage 2': thread (k0, n0), IDFT over k1 -> n1,
  //      twiddle e^{+2pi i (8*n1+n0)*k0/512}
#pragma unroll
  for (int j = 0; j < 8; ++j) { float2 f = sm[s][swz(k0, j, n0)]; v[j] = {f.x, f.y}; }
  dft8<1>(v);
  {
    float sn, cs;
    __sincosf(2.f * PIf * (float)(k0 * n0) * (1.f / 512.f), &sn, &cs);
    cplx w0{cs, sn};
    __sincosf(2.f * PIf * (float)k0 * (1.f / 64.f), &sn, &cs);
    cplx ws{cs, sn};
#pragma unroll
    for (int n1 = 0; n1 < 8; ++n1) { v[n1] = cmul(v[n1], w0); if (n1 < 7) w0 = cmul(w0, ws); }
  }
#pragma unroll
  for (int n1 = 0; n1 < 8; ++n1)
    sm[s][swz(k0, n1, n0)] = make_float2(v[n1].x, v[n1].y);
  __syncthreads();

  // ---- inverse stage 1': thread t=(n1,n0), IDFT over k0 -> n2, store
#pragma unroll
  for (int a = 0; a < 8; ++a) { float2 f = sm[s][swz(a, t >> 3, t & 7)]; v[a] = {f.x, f.y}; }
  dft8<1>(v);

  float* __restrict__ o1 = out + row1;
  float* __restrict__ o2 = out + row2;
#pragma unroll
  for (int n2 = 0; n2 < 8; ++n2) {
    o1[(n2 << 6) + t] = v[n2].x;   // Re -> batch s
    o2[(n2 << 6) + t] = v[n2].y;   // Im -> batch s+4
  }
}

} // namespace

extern "C" void kernel_launch(void* const* d_in, const int* in_sizes, int n_in,
                              void* d_out, int out_size) {
  const float* x   = (const float*)d_in[0];
  // d_in[1] is the (unused) mask
  const float* wgt = (const float*)d_in[2];
  float* out       = (float*)d_out;
  sgn_fft_kernel<<<Hh * Ll, 256>>>(x, wgt, out);
}

// round 3
// speedup vs baseline: 1.5668x; 1.2950x over previous
#include <cuda_runtime.h>

namespace {

constexpr int Hh = 8, Ll = 2048, Dd = 512;
constexpr float PIf = 3.14159265358979323846f;

struct cplx { float x, y; };
__device__ __forceinline__ cplx cadd(cplx a, cplx b){ return {a.x+b.x, a.y+b.y}; }
__device__ __forceinline__ cplx csub(cplx a, cplx b){ return {a.x-b.x, a.y-b.y}; }
__device__ __forceinline__ cplx cmul(cplx a, cplx b){ return {a.x*b.x - a.y*b.y, a.x*b.y + a.y*b.x}; }

// 8-point DFT, natural order in/out. S = -1 forward, +1 inverse.
template<int S>
__device__ __forceinline__ void dft8(cplx v[8]) {
  const float r = 0.70710678118654752440f;
  cplx a0=cadd(v[0],v[4]), a1=cadd(v[1],v[5]), a2=cadd(v[2],v[6]), a3=cadd(v[3],v[7]);
  cplx b0=csub(v[0],v[4]), b1=csub(v[1],v[5]), b2=csub(v[2],v[6]), b3=csub(v[3],v[7]);
  b1 = cmul(b1, cplx{ r, S * r});
  b2 = (S < 0) ? cplx{ b2.y, -b2.x} : cplx{-b2.y, b2.x};
  b3 = cmul(b3, cplx{-r, S * r});
  cplx e0=cadd(a0,a2), e1=cadd(a1,a3), o0=csub(a0,a2);
  cplx t1=csub(a1,a3);
  cplx o1 = (S < 0) ? cplx{ t1.y, -t1.x} : cplx{-t1.y, t1.x};
  v[0]=cadd(e0,e1); v[4]=csub(e0,e1); v[2]=cadd(o0,o1); v[6]=csub(o0,o1);
  cplx f0=cadd(b0,b2), f1=cadd(b1,b3), p0=csub(b0,b2);
  cplx t2=csub(b1,b3);
  cplx p1 = (S < 0) ? cplx{ t2.y, -t2.x} : cplx{-t2.y, t2.x};
  v[1]=cadd(f0,f1); v[5]=csub(f0,f1); v[3]=cadd(p0,p1); v[7]=csub(p0,p1);
}

// Phase-conflict-free swizzle for logical index 64a + 8b + c (a,b,c in 0..7).
// phys bits [8:4] = (a2,a1,b2,b1,b0); bits [3:0] = (a0^b0, c2^b2, c1^b1, c0^b0).
// For each access pattern's half-warp free-bit subspace (S1={b0,c}, S2={a0,c},
// S3={a0,b}, gate={c0,b}) the low-4 map is invertible => 16 lanes hit 16
// distinct bank-pairs => exactly 2 wavefronts per 8B instruction (the floor).
__device__ __forceinline__ int swz(int a, int b, int c) {
  return ((a >> 1) << 7) | ((b >> 1) << 5) | ((b & 1) << 4)
       | (((a ^ b) & 1) << 3) | ((b ^ c) & 7);
}

// One block = one (h,l): 4 pair-rows (pb pairs batches pb and pb+4),
// 64 threads per pair-row. Radix-8 FFT512 (DIF fwd, digit-rev spectrum,
// DIT inv). Symmetrized gate V staged into smem once per block, stored in
// swizzled digit-reversed layout so staging and gate reads are conflict-free.
__global__ void __launch_bounds__(256)
sgn_fft_kernel(const float* __restrict__ x, const float* __restrict__ wgt,
               float* __restrict__ out)
{
  __shared__ float2 sm[4][512];
  __shared__ float2 Vsm[512];

  const int tid = threadIdx.x;
  const int s   = tid >> 6;
  const int t   = tid & 63;
  const int hl  = blockIdx.x;
  const int h   = hl >> 11;
  const int l   = hl & 2047;

  const float2* __restrict__ wrow =
      reinterpret_cast<const float2*>(wgt) + (size_t)(h * Ll + l) * Dd;

  // ---- stage gate: V_k = (W_k + conj(W_{-k})) / 1024, stored at
  // phys(a=k2, b=k1, c=k0) for k = k0 + 8*k1 + 64*k2. Ordered before first
  // use by the stage-1 __syncthreads below.
#pragma unroll
  for (int i = tid; i < 512; i += 256) {
    float2 wk = __ldg(&wrow[i]);
    float2 wm = __ldg(&wrow[(512 - i) & 511]);
    Vsm[swz(i >> 6, (i >> 3) & 7, i & 7)] =
        make_float2((wk.x + wm.x) * (1.f / 1024.f),
                    (wk.y - wm.y) * (1.f / 1024.f));
  }

  const size_t row1 = ((size_t)(((s    ) * Hh + h) * Ll + l)) * Dd;
  const size_t row2 = ((size_t)(((s + 4) * Hh + h) * Ll + l)) * Dd;
  const float* __restrict__ x1 = x + row1;
  const float* __restrict__ x2 = x + row2;

  cplx v[8];
  // z = x1 + i*x2, n = 64*n2 + t
#pragma unroll
  for (int n2 = 0; n2 < 8; ++n2) {
    v[n2].x = __ldg(&x1[(n2 << 6) + t]);
    v[n2].y = __ldg(&x2[(n2 << 6) + t]);
  }

  // ---- forward stage 1: DFT over n2 -> k0, twiddle e^{-2pi i t k0/512}
  dft8<-1>(v);
  {
    float sn, cs; __sincosf(-2.f * PIf * (float)t * (1.f / 512.f), &sn, &cs);
    cplx w1{cs, sn}, wk = w1;
#pragma unroll
    for (int k = 1; k < 8; ++k) { v[k] = cmul(v[k], wk); if (k < 7) wk = cmul(wk, w1); }
  }
  {
    const int n1 = t >> 3, n0 = t & 7;
#pragma unroll
    for (int k = 0; k < 8; ++k)
      sm[s][swz(k, n1, n0)] = make_float2(v[k].x, v[k].y);
  }
  __syncthreads();

  // ---- forward stage 2: thread (k0, n0), DFT over n1 -> k1, twiddle e^{-2pi i n0 k1/64}
  const int k0 = t >> 3;
  const int n0 = t & 7;
#pragma unroll
  for (int j = 0; j < 8; ++j) { float2 f = sm[s][swz(k0, j, n0)]; v[j] = {f.x, f.y}; }
  dft8<-1>(v);
  {
    float sn, cs; __sincosf(-2.f * PIf * (float)n0 * (1.f / 64.f), &sn, &cs);
    cplx w1{cs, sn}, wk = w1;
#pragma unroll
    for (int k = 1; k < 8; ++k) { v[k] = cmul(v[k], wk); if (k < 7) wk = cmul(wk, w1); }
  }
#pragma unroll
  for (int k = 0; k < 8; ++k)
    sm[s][swz(k0, k, n0)] = make_float2(v[k].x, v[k].y);
  __syncthreads();

  // ---- forward stage 3 (registers): thread (k0, k1), DFT over n0 -> k2
  const int k1 = t & 7;
#pragma unroll
  for (int c = 0; c < 8; ++c) { float2 f = sm[s][swz(k0, k1, c)]; v[c] = {f.x, f.y}; }
  dft8<-1>(v);
  // v[k2] = Z[k] at k = k0 + 8*k1 + 64*k2

  // ---- spectral gate from swizzled smem (conflict-free)
#pragma unroll
  for (int k2 = 0; k2 < 8; ++k2) {
    float2 Vv = Vsm[swz(k2, k1, k0)];
    v[k2] = cmul(v[k2], cplx{Vv.x, Vv.y});
  }

  // ---- inverse stage 3': IDFT over k2 -> n0', twiddle e^{+2pi i n0' k1/64}
  dft8<1>(v);
  {
    float sn, cs; __sincosf(2.f * PIf * (float)k1 * (1.f / 64.f), &sn, &cs);
    cplx w1{cs, sn}, wk = w1;
#pragma unroll
    for (int n = 1; n < 8; ++n) { v[n] = cmul(v[n], wk); if (n < 7) wk = cmul(wk, w1); }
  }
#pragma unroll
  for (int c = 0; c < 8; ++c)
    sm[s][swz(k0, k1, c)] = make_float2(v[c].x, v[c].y);
  __syncthreads();

  // ---- inverse stage 2': thread (k0, n0), IDFT over k1 -> n1,
  //      twiddle e^{+2pi i (8*n1+n0)*k0/512}
#pragma unroll
  for (int j = 0; j < 8; ++j) { float2 f = sm[s][swz(k0, j, n0)]; v[j] = {f.x, f.y}; }
  dft8<1>(v);
  {
    float sn, cs;
    __sincosf(2.f * PIf * (float)(k0 * n0) * (1.f / 512.f), &sn, &cs);
    cplx w0{cs, sn};
    __sincosf(2.f * PIf * (float)k0 * (1.f / 64.f), &sn, &cs);
    cplx ws{cs, sn};
#pragma unroll
    for (int n1 = 0; n1 < 8; ++n1) { v[n1] = cmul(v[n1], w0); if (n1 < 7) w0 = cmul(w0, ws); }
  }
#pragma unroll
  for (int n1 = 0; n1 < 8; ++n1)
    sm[s][swz(k0, n1, n0)] = make_float2(v[n1].x, v[n1].y);
  __syncthreads();

  // ---- inverse stage 1': thread t=(n1,n0), IDFT over k0 -> n2, store
#pragma unroll
  for (int a = 0; a < 8; ++a) { float2 f = sm[s][swz(a, t >> 3, t & 7)]; v[a] = {f.x, f.y}; }
  dft8<1>(v);

  float* __restrict__ o1 = out + row1;
  float* __restrict__ o2 = out + row2;
#pragma unroll
  for (int n2 = 0; n2 < 8; ++n2) {
    o1[(n2 << 6) + t] = v[n2].x;   // Re -> batch s
    o2[(n2 << 6) + t] = v[n2].y;   // Im -> batch s+4
  }
}

} // namespace

extern "C" void kernel_launch(void* const* d_in, const int* in_sizes, int n_in,
                              void* d_out, int out_size) {
  const float* x   = (const float*)d_in[0];
  // d_in[1] is the (unused) mask
  const float* wgt = (const float*)d_in[2];
  float* out       = (float*)d_out;
  sgn_fft_kernel<<<Hh * Ll, 256>>>(x, wgt, out);
}

// round 4
// speedup vs baseline: 1.7644x; 1.1261x over previous
#include <cuda_runtime.h>

namespace {

constexpr int Hh = 8, Ll = 2048, Dd = 512;
constexpr float PIf = 3.14159265358979323846f;
using u64 = unsigned long long;

// ---- packed f32x2 complex ops (re in lane0, im in lane1) -------------------
__device__ __forceinline__ u64 pk2(float x, float y) {
  u64 r; asm("mov.b64 %0, {%1, %2};" : "=l"(r) : "f"(x), "f"(y)); return r;
}
__device__ __forceinline__ void unpk(u64 v, float& x, float& y) {
  asm("mov.b64 {%0, %1}, %2;" : "=f"(x), "=f"(y) : "l"(v));
}
__device__ __forceinline__ u64 padd(u64 a, u64 b) {
  u64 r; asm("add.rn.f32x2 %0, %1, %2;" : "=l"(r) : "l"(a), "l"(b)); return r;
}
__device__ __forceinline__ u64 pmul(u64 a, u64 b) {
  u64 r; asm("mul.rn.f32x2 %0, %1, %2;" : "=l"(r) : "l"(a), "l"(b)); return r;
}
__device__ __forceinline__ u64 pfma(u64 a, u64 b, u64 c) {
  u64 r; asm("fma.rn.f32x2 %0, %1, %2, %3;" : "=l"(r) : "l"(a), "l"(b), "l"(c)); return r;
}
__device__ __forceinline__ u64 pswap(u64 v) { float x, y; unpk(v, x, y); return pk2(y, x); }
// multiply by -i (S=-1) or +i (S=+1)
template<int S>
__device__ __forceinline__ u64 prot(u64 v) {
  float x, y; unpk(v, x, y);
  return (S < 0) ? pk2(y, -x) : pk2(-y, x);
}
// scalar-twiddle complex multiply on a packed value
__device__ __forceinline__ u64 cmulsc(u64 v, float c, float s) {
  float x, y; unpk(v, x, y);
  return pk2(x * c - y * s, x * s + y * c);
}

// 8-point DFT on packed values, natural order. S=-1 forward, +1 inverse.
template<int S>
__device__ __forceinline__ void dft8p(u64 v[8]) {
  const float r = 0.70710678118654752440f;
  const u64 NEG1 = pk2(-1.f, -1.f);
  const u64 PM   = pk2( 1.f, -1.f);
  const u64 MP   = pk2(-1.f,  1.f);
  const u64 RR   = pk2(  r,    r);
  const u64 NR   = pk2( -r,   -r);
  auto psub = [&](u64 a, u64 b) { return pfma(b, NEG1, a); };

  u64 a0 = padd(v[0], v[4]), a1 = padd(v[1], v[5]);
  u64 a2 = padd(v[2], v[6]), a3 = padd(v[3], v[7]);
  u64 b0 = psub(v[0], v[4]), b1 = psub(v[1], v[5]);
  u64 b2 = psub(v[2], v[6]), b3 = psub(v[3], v[7]);

  // b1 *= W8^S ; b3 *= W8^{3S} ; b2 *= (-+i)
  b1 = pmul(pfma(pswap(b1), (S < 0) ? PM : MP, b1), RR);
  b3 = pmul(pfma(pswap(b3), (S < 0) ? MP : PM, b3), NR);
  b2 = prot<S>(b2);

  // DFT4 on a -> even outputs
  {
    u64 e0 = padd(a0, a2), e1 = padd(a1, a3);
    u64 o0 = psub(a0, a2), t1 = psub(a1, a3);
    u64 o1 = prot<S>(t1);
    v[0] = padd(e0, e1); v[4] = psub(e0, e1);
    v[2] = padd(o0, o1); v[6] = psub(o0, o1);
  }
  // DFT4 on b -> odd outputs
  {
    u64 e0 = padd(b0, b2), e1 = padd(b1, b3);
    u64 o0 = psub(b0, b2), t1 = psub(b1, b3);
    u64 o1 = prot<S>(t1);
    v[1] = padd(e0, e1); v[5] = psub(e0, e1);
    v[3] = padd(o0, o1); v[7] = psub(o0, o1);
  }
}

// Phase-conflict-free swizzle for logical index 64a + 8b + c (a,b,c in 0..7).
// phys [8:4] = (a2,a1,b2,b1,b0); [3:0] = (a0^b0, c2^b2, c1^b1, c0^b0).
// Invertible on each access pattern's half-warp free-bit subspace =>
// 2 wavefronts per 8B instruction (the floor) on every exchange and the gate.
__device__ __forceinline__ int swz(int a, int b, int c) {
  return ((a >> 1) << 7) | ((b >> 1) << 5) | ((b & 1) << 4)
       | (((a ^ b) & 1) << 3) | ((b ^ c) & 7);
}

// One block = one (h,l): 4 pair-rows (s pairs batches s and s+4),
// 64 threads per pair-row. Radix-8 FFT512 (DIF fwd, digit-rev spectrum,
// DIT inv). Gate staged in smem (swizzled digit-reversed layout).
__global__ void __launch_bounds__(256, 5)
sgn_fft_kernel(const float* __restrict__ x, const float* __restrict__ wgt,
               float* __restrict__ out)
{
  __shared__ u64 sm[4][512];
  __shared__ float2 Vsm[512];

  const int tid = threadIdx.x;
  const int s   = tid >> 6;
  const int t   = tid & 63;
  const int hl  = blockIdx.x;
  const int h   = hl >> 11;
  const int l   = hl & 2047;

  const float2* __restrict__ wrow =
      reinterpret_cast<const float2*>(wgt) + (size_t)(h * Ll + l) * Dd;

  // V_k = (W_k + conj(W_{-k})) / 1024, stored at phys(a=k2,b=k1,c=k0).
#pragma unroll
  for (int i = tid; i < 512; i += 256) {
    float2 wk = __ldg(&wrow[i]);
    float2 wm = __ldg(&wrow[(512 - i) & 511]);
    Vsm[swz(i >> 6, (i >> 3) & 7, i & 7)] =
        make_float2((wk.x + wm.x) * (1.f / 1024.f),
                    (wk.y - wm.y) * (1.f / 1024.f));
  }

  const size_t row1 = ((size_t)(((s    ) * Hh + h) * Ll + l)) * Dd;
  const size_t row2 = ((size_t)(((s + 4) * Hh + h) * Ll + l)) * Dd;
  const float* __restrict__ x1 = x + row1;
  const float* __restrict__ x2 = x + row2;

  u64 v[8];
  // z = x1 + i*x2, n = 64*n2 + t
#pragma unroll
  for (int n2 = 0; n2 < 8; ++n2)
    v[n2] = pk2(__ldg(&x1[(n2 << 6) + t]), __ldg(&x2[(n2 << 6) + t]));

  // ---- forward stage 1: DFT over n2 -> k0, twiddle e^{-2pi i t k0/512}
  dft8p<-1>(v);
  {
    float s1, c1; __sincosf(-2.f * PIf * (float)t * (1.f / 512.f), &s1, &c1);
    float cc = c1, ss = s1;
#pragma unroll
    for (int k = 1; k < 8; ++k) {
      v[k] = cmulsc(v[k], cc, ss);
      if (k < 7) { float nc = cc * c1 - ss * s1; ss = cc * s1 + ss * c1; cc = nc; }
    }
  }
  {
    const int n1 = t >> 3, n0 = t & 7;
#pragma unroll
    for (int k = 0; k < 8; ++k) sm[s][swz(k, n1, n0)] = v[k];
  }
  __syncthreads();

  // ---- forward stage 2: thread (k0, n0), DFT over n1 -> k1, tw e^{-2pi i n0 k1/64}
  const int k0 = t >> 3;
  const int n0 = t & 7;
#pragma unroll
  for (int j = 0; j < 8; ++j) v[j] = sm[s][swz(k0, j, n0)];
  dft8p<-1>(v);
  {
    float s1, c1; __sincosf(-2.f * PIf * (float)n0 * (1.f / 64.f), &s1, &c1);
    float cc = c1, ss = s1;
#pragma unroll
    for (int k = 1; k < 8; ++k) {
      v[k] = cmulsc(v[k], cc, ss);
      if (k < 7) { float nc = cc * c1 - ss * s1; ss = cc * s1 + ss * c1; cc = nc; }
    }
  }
#pragma unroll
  for (int k = 0; k < 8; ++k) sm[s][swz(k0, k, n0)] = v[k];
  __syncthreads();

  // ---- forward stage 3 (registers): thread (k0, k1), DFT over n0 -> k2
  const int k1 = t & 7;
#pragma unroll
  for (int c = 0; c < 8; ++c) v[c] = sm[s][swz(k0, k1, c)];
  dft8p<-1>(v);
  // v[k2] = Z[k] at k = k0 + 8*k1 + 64*k2

  // ---- spectral gate (conflict-free smem)
#pragma unroll
  for (int k2 = 0; k2 < 8; ++k2) {
    float2 Vv = Vsm[swz(k2, k1, k0)];
    v[k2] = cmulsc(v[k2], Vv.x, Vv.y);
  }

  // ---- inverse stage 3': IDFT over k2 -> n0', twiddle e^{+2pi i n0' k1/64}
  dft8p<1>(v);
  {
    float s1, c1; __sincosf(2.f * PIf * (float)k1 * (1.f / 64.f), &s1, &c1);
    float cc = c1, ss = s1;
#pragma unroll
    for (int n = 1; n < 8; ++n) {
      v[n] = cmulsc(v[n], cc, ss);
      if (n < 7) { float nc = cc * c1 - ss * s1; ss = cc * s1 + ss * c1; cc = nc; }
    }
  }
#pragma unroll
  for (int c = 0; c < 8; ++c) sm[s][swz(k0, k1, c)] = v[c];
  __syncthreads();

  // ---- inverse stage 2': thread (k0, n0), IDFT over k1 -> n1,
  //      twiddle e^{+2pi i (8*n1+n0)*k0/512}
#pragma unroll
  for (int j = 0; j < 8; ++j) v[j] = sm[s][swz(k0, j, n0)];
  dft8p<1>(v);
  {
    float s0, c0; __sincosf(2.f * PIf * (float)(k0 * n0) * (1.f / 512.f), &s0, &c0);
    float s1, c1; __sincosf(2.f * PIf * (float)k0 * (1.f / 64.f), &s1, &c1);
    float cc = c0, ss = s0;
#pragma unroll
    for (int n1 = 0; n1 < 8; ++n1) {
      v[n1] = cmulsc(v[n1], cc, ss);
      if (n1 < 7) { float nc = cc * c1 - ss * s1; ss = cc * s1 + ss * c1; cc = nc; }
    }
  }
#pragma unroll
  for (int n1 = 0; n1 < 8; ++n1) sm[s][swz(k0, n1, n0)] = v[n1];
  __syncthreads();

  // ---- inverse stage 1': thread t=(n1,n0), IDFT over k0 -> n2, store
#pragma unroll
  for (int a = 0; a < 8; ++a) v[a] = sm[s][swz(a, t >> 3, t & 7)];
  dft8p<1>(v);

  float* __restrict__ o1 = out + row1;
  float* __restrict__ o2 = out + row2;
#pragma unroll
  for (int n2 = 0; n2 < 8; ++n2) {
    float re, im; unpk(v[n2], re, im);
    o1[(n2 << 6) + t] = re;   // Re -> batch s
    o2[(n2 << 6) + t] = im;   // Im -> batch s+4
  }
}

} // namespace

extern "C" void kernel_launch(void* const* d_in, const int* in_sizes, int n_in,
                              void* d_out, int out_size) {
  const float* x   = (const float*)d_in[0];
  // d_in[1] is the (unused) mask
  const float* wgt = (const float*)d_in[2];
  float* out       = (float*)d_out;
  sgn_fft_kernel<<<Hh * Ll, 256>>>(x, wgt, out);
}